// round 4
// baseline (speedup 1.0000x reference)
#include <cuda_runtime.h>

#define S 26
#define D 7
#define DA 11
#define V 29
#define NT 832   // 26 warps: one warp per sequence row

__global__ __launch_bounds__(NT, 1)
void bes_transformer_kernel(
    const int*   __restrict__ x,
    const float* __restrict__ emb_table,
    const float* __restrict__ pos,
    const float* __restrict__ wk0, const float* __restrict__ bk0,
    const float* __restrict__ wq0, const float* __restrict__ bq0,
    const float* __restrict__ wv0, const float* __restrict__ bv0,
    const float* __restrict__ wf0, const float* __restrict__ bf0,
    const float* __restrict__ wk1, const float* __restrict__ bk1,
    const float* __restrict__ wq1, const float* __restrict__ bq1,
    const float* __restrict__ wv1, const float* __restrict__ bv1,
    const float* __restrict__ wf1, const float* __restrict__ bf1,
    const float* __restrict__ wout, const float* __restrict__ bout,
    float* __restrict__ out)
{
    __shared__ float h[S][D];
    __shared__ float k[S][DA];
    __shared__ float q[S][DA];
    __shared__ float v[S][DA];
    __shared__ float att[S][S];   // exp(q.k), lower triangle only
    __shared__ float res[S][DA];
    __shared__ float inv[S];      // 1 / row-sum

    const int t    = threadIdx.x;
    const int r    = t >> 5;      // warp id == row id (0..25)
    const int lane = t & 31;

    // ---- embedding + positional (182 elems, single shot) ----
    if (t < S * D) {
        int s = t / D, d = t % D;
        h[s][d] = emb_table[x[s] * D + d] + pos[t];
    }
    __syncthreads();

    #pragma unroll
    for (int layer = 0; layer < 2; layer++) {
        const float* wk = layer ? wk1 : wk0;
        const float* bk = layer ? bk1 : bk0;
        const float* wq = layer ? wq1 : wq0;
        const float* bq = layer ? bq1 : bq0;
        const float* wv = layer ? wv1 : wv0;
        const float* bv = layer ? bv1 : bv0;
        const float* wf = layer ? wf1 : wf0;
        const float* bf = layer ? bf1 : bf0;

        // ---- K, Q, V projections (286 elems, single shot, warps 0-8) ----
        if (t < S * DA) {
            int s = t / DA, a = t % DA;
            float sk = bk[a], sq = bq[a], sv = bv[a];
            #pragma unroll
            for (int d = 0; d < D; d++) {
                float hv = h[s][d];
                sk += hv * wk[a * D + d];
                sq += hv * wq[a * D + d];
                sv += hv * wv[a * D + d];
            }
            k[s][a] = sk; q[s][a] = sq; v[s][a] = sv;
        }
        __syncthreads();

        // ======== per-row attention: warp r owns row r ========
        // scores + exp: lane c computes exp(q[r].k[c]) for c <= r
        if (lane <= r) {
            float sum = 0.f;
            #pragma unroll
            for (int a = 0; a < DA; a++) sum += q[r][a] * k[lane][a];
            att[r][lane] = __expf(sum);
        }
        __syncwarp();

        // fused row-sum + AV + normalize: lane a computes res[r][a]
        if (lane < DA) {
            float sum = 0.f, dot = 0.f;
            for (int c = 0; c <= r; c++) {
                float e = att[r][c];
                sum += e;
                dot += e * v[c][lane];
            }
            float iv = __frcp_rn(sum);
            res[r][lane] = dot * iv;
            if (lane == 0) inv[r] = iv;
        }
        __syncwarp();

        // output projection: lane d computes h[r][d]
        if (lane < D) {
            float val = bf[lane];
            #pragma unroll
            for (int a = 0; a < DA; a++) val += res[r][a] * wf[lane * DA + a];
            h[r][lane] = val;
        }

        // layer-1 attention matrix goes straight to output (no extra barrier)
        if (layer == 1 && lane < S) {
            out[S * V + r * S + lane] = (lane <= r) ? att[r][lane] * inv[r] : 0.f;
        }
        __syncthreads();
    }

    // ---- logits: out = h @ wout^T + bout (754 elems, single shot) ----
    if (t < S * V) {
        int s = t / V, vv = t % V;
        float val = bout[vv];
        #pragma unroll
        for (int d = 0; d < D; d++) val += h[s][d] * wout[vv * D + d];
        out[t] = val;
    }
}

extern "C" void kernel_launch(void* const* d_in, const int* in_sizes, int n_in,
                              void* d_out, int out_size)
{
    bes_transformer_kernel<<<1, NT>>>(
        (const int*)  d_in[0],   // x
        (const float*)d_in[1],   // emb_table
        (const float*)d_in[2],   // pos
        (const float*)d_in[3],  (const float*)d_in[4],   // w_k0, b_k0
        (const float*)d_in[5],  (const float*)d_in[6],   // w_q0, b_q0
        (const float*)d_in[7],  (const float*)d_in[8],   // w_v0, b_v0
        (const float*)d_in[9],  (const float*)d_in[10],  // w_f0, b_f0
        (const float*)d_in[11], (const float*)d_in[12],  // w_k1, b_k1
        (const float*)d_in[13], (const float*)d_in[14],  // w_q1, b_q1
        (const float*)d_in[15], (const float*)d_in[16],  // w_v1, b_v1
        (const float*)d_in[17], (const float*)d_in[18],  // w_f1, b_f1
        (const float*)d_in[19], (const float*)d_in[20],  // w_out, b_out
        (float*)d_out);
}